// round 1
// baseline (speedup 1.0000x reference)
#include <cuda_runtime.h>
#include <math.h>

// Problem constants
#define NB   4
#define CCH  512
#define SEQ  4096
#define D3   1536
#define GRP  32
#define CPG  16     // channels per group

// ---------------- scratch (static device arrays; no allocs allowed) ---------
__device__ float g_seq[(size_t)NB * CCH * SEQ];       // groupnormed x, [n][c][s]
__device__ float g_qkv[(size_t)NB * D3 * SEQ];        // [n][d][s] (q:0..511, k:512..1023, v:1024..1535)
__device__ float g_scores[(size_t)NB * SEQ * SEQ];    // [n][s][t]
__device__ float g_att[(size_t)NB * CCH * SEQ];       // attn @ V, transposed [n][c][s]

// ---------------- block reduction helper ------------------------------------
__device__ __forceinline__ float block_reduce(float v, float* sh, bool is_max) {
    int lane = threadIdx.x & 31;
    int wid  = threadIdx.x >> 5;
#pragma unroll
    for (int o = 16; o > 0; o >>= 1) {
        float other = __shfl_xor_sync(0xffffffffu, v, o);
        v = is_max ? fmaxf(v, other) : (v + other);
    }
    if (lane == 0) sh[wid] = v;
    __syncthreads();
    if (threadIdx.x < 32) {
        float w = (threadIdx.x < 8) ? sh[threadIdx.x] : (is_max ? -3.402823e38f : 0.0f);
#pragma unroll
        for (int o = 4; o > 0; o >>= 1) {
            float other = __shfl_xor_sync(0xffffffffu, w, o);
            w = is_max ? fmaxf(w, other) : (w + other);
        }
        if (threadIdx.x == 0) sh[0] = w;
    }
    __syncthreads();
    float r = sh[0];
    __syncthreads();
    return r;
}

// ---------------- GroupNorm --------------------------------------------------
// one block per (n, group): reduce over CPG*SEQ = 65536 elements
__global__ void groupnorm_kernel(const float* __restrict__ x,
                                 const float* __restrict__ gamma,
                                 const float* __restrict__ beta,
                                 float* __restrict__ seq_out) {
    __shared__ float sh[8];
    int n = blockIdx.x >> 5;
    int g = blockIdx.x & 31;
    const size_t base = ((size_t)n * CCH + (size_t)g * CPG) * SEQ;
    const float* xb = x + base;
    float* ob = seq_out + base;

    float s = 0.f, s2 = 0.f;
    for (int i = threadIdx.x; i < CPG * SEQ; i += 256) {
        float v = xb[i];
        s  += v;
        s2 += v * v;
    }
    s  = block_reduce(s,  sh, false);
    s2 = block_reduce(s2, sh, false);

    const float invn = 1.0f / (float)(CPG * SEQ);
    float mean = s * invn;
    float var  = s2 * invn - mean * mean;
    float rstd = rsqrtf(var + 1e-5f);

    for (int i = threadIdx.x; i < CPG * SEQ; i += 256) {
        int c = g * CPG + (i >> 12);           // SEQ = 4096 = 2^12
        float v = (xb[i] - mean) * rstd;
        ob[i] = v * gamma[c] + beta[c];
    }
}

// ---------------- generic tiled SGEMM ---------------------------------------
// C[m,n] = alpha * sum_k A(m,k) * B(n,k)   (logical; layouts below)
// A_KM:  A stored [K, M] (lda = stride between k rows, m contiguous)
//       else A stored [M, K] (lda = stride between m rows, k contiguous)
// B_KM:  B stored [K, N] (ldb = k-row stride, n contiguous)
//       else B stored [N, K] (ldb = n-row stride, k contiguous)
// TRANS_OUT: write C[n*ldc + m] (output [N, M]); else C[m*ldc + n]
// M, N multiples of 64; K multiple of 16 (true for all our shapes).
template<bool A_KM, bool B_KM, bool TRANS_OUT, bool HAS_BIAS, bool HAS_RES>
__global__ void gemm_kernel(const float* __restrict__ A,
                            const float* __restrict__ B,
                            float* __restrict__ C,
                            const float* __restrict__ bias,
                            const float* __restrict__ resid,
                            int M, int N, int K,
                            int lda, int ldb, int ldc,
                            long batchA, long batchB, long batchC, long batchRes,
                            float alpha) {
    __shared__ float As[16][68];
    __shared__ float Bs[16][68];

    A += (long)blockIdx.z * batchA;
    B += (long)blockIdx.z * batchB;
    C += (long)blockIdx.z * batchC;
    if (HAS_RES) resid += (long)blockIdx.z * batchRes;

    const int m0 = blockIdx.y * 64;
    const int n0 = blockIdx.x * 64;
    const int tid = threadIdx.x;
    const int tx = tid & 15;
    const int ty = tid >> 4;

    float acc[4][4];
#pragma unroll
    for (int i = 0; i < 4; i++)
#pragma unroll
        for (int j = 0; j < 4; j++) acc[i][j] = 0.f;

    for (int k0 = 0; k0 < K; k0 += 16) {
        // load A tile -> As[k][m]
#pragma unroll
        for (int j = 0; j < 4; j++) {
            int e = tid + j * 256;
            if (A_KM) {
                int kk = e >> 6, mm = e & 63;
                As[kk][mm] = A[(long)(k0 + kk) * lda + (m0 + mm)];
            } else {
                int kk = e & 15, mm = e >> 4;
                As[kk][mm] = A[(long)(m0 + mm) * lda + (k0 + kk)];
            }
        }
        // load B tile -> Bs[k][n]
#pragma unroll
        for (int j = 0; j < 4; j++) {
            int e = tid + j * 256;
            if (B_KM) {
                int kk = e >> 6, nn = e & 63;
                Bs[kk][nn] = B[(long)(k0 + kk) * ldb + (n0 + nn)];
            } else {
                int kk = e & 15, nn = e >> 4;
                Bs[kk][nn] = B[(long)(n0 + nn) * ldb + (k0 + kk)];
            }
        }
        __syncthreads();

#pragma unroll
        for (int kk = 0; kk < 16; kk++) {
            float4 a = *(const float4*)&As[kk][ty * 4];
            float4 b = *(const float4*)&Bs[kk][tx * 4];
            float av[4] = {a.x, a.y, a.z, a.w};
            float bv[4] = {b.x, b.y, b.z, b.w};
#pragma unroll
            for (int i = 0; i < 4; i++)
#pragma unroll
                for (int j = 0; j < 4; j++)
                    acc[i][j] = fmaf(av[i], bv[j], acc[i][j]);
        }
        __syncthreads();
    }

    // epilogue
#pragma unroll
    for (int i = 0; i < 4; i++) {
        int m = m0 + ty * 4 + i;
#pragma unroll
        for (int j = 0; j < 4; j++) {
            int n = n0 + tx * 4 + j;
            float v = acc[i][j] * alpha;
            if (HAS_BIAS) v += bias[n];
            if (TRANS_OUT) {
                long idx = (long)n * ldc + m;
                if (HAS_RES) v += resid[idx];
                C[idx] = v;
            } else {
                long idx = (long)m * ldc + n;
                if (HAS_RES) v += resid[idx];
                C[idx] = v;
            }
        }
    }
}

// ---------------- row softmax -----------------------------------------------
// one block per row of 4096; values held in registers (1 read + 1 write)
__global__ void softmax_kernel(float* __restrict__ scores) {
    __shared__ float sh[8];
    float* p = scores + (long)blockIdx.x * SEQ;
    const int tid = threadIdx.x;

    float v[16];
    float mx = -3.402823e38f;
#pragma unroll
    for (int j = 0; j < 16; j++) {
        v[j] = p[j * 256 + tid];
        mx = fmaxf(mx, v[j]);
    }
    mx = block_reduce(mx, sh, true);

    float sum = 0.f;
#pragma unroll
    for (int j = 0; j < 16; j++) {
        v[j] = __expf(v[j] - mx);
        sum += v[j];
    }
    sum = block_reduce(sum, sh, false);
    float inv = 1.0f / sum;

#pragma unroll
    for (int j = 0; j < 16; j++)
        p[j * 256 + tid] = v[j] * inv;
}

// ---------------- launch ------------------------------------------------------
extern "C" void kernel_launch(void* const* d_in, const int* in_sizes, int n_in,
                              void* d_out, int out_size) {
    const float* x        = (const float*)d_in[0];
    const float* gn_scale = (const float*)d_in[1];
    const float* gn_bias  = (const float*)d_in[2];
    const float* w_in     = (const float*)d_in[3];
    const float* b_in     = (const float*)d_in[4];
    const float* w_out    = (const float*)d_in[5];
    const float* b_out    = (const float*)d_in[6];
    float* out = (float*)d_out;

    float *seq, *qkv, *scores, *att;
    cudaGetSymbolAddress((void**)&seq,    g_seq);
    cudaGetSymbolAddress((void**)&qkv,    g_qkv);
    cudaGetSymbolAddress((void**)&scores, g_scores);
    cudaGetSymbolAddress((void**)&att,    g_att);

    // 1) GroupNorm -> g_seq [n][c][s]
    groupnorm_kernel<<<NB * GRP, 256>>>(x, gn_scale, gn_bias, seq);

    // 2) QKV projection: qkv[n][d][s] = sum_c seq[n][c][s] * w_in[d][c] + b_in[d]
    {
        dim3 grid(D3 / 64, SEQ / 64, NB);
        gemm_kernel<true, false, true, true, false><<<grid, 256>>>(
            seq, w_in, qkv, b_in, nullptr,
            SEQ, D3, CCH,
            SEQ, CCH, SEQ,
            (long)CCH * SEQ, 0, (long)D3 * SEQ, 0, 1.0f);
    }

    // 3) scores[n][s][t] = scale * sum_c q[n][c][s] * k[n][c][t]
    {
        dim3 grid(SEQ / 64, SEQ / 64, NB);
        const float scale = 0.044194173824159216f;  // 1/sqrt(512)
        gemm_kernel<true, true, false, false, false><<<grid, 256>>>(
            qkv, qkv + (size_t)CCH * SEQ, scores, nullptr, nullptr,
            SEQ, SEQ, CCH,
            SEQ, SEQ, SEQ,
            (long)D3 * SEQ, (long)D3 * SEQ, (long)SEQ * SEQ, 0, scale);
    }

    // 4) softmax over t
    softmax_kernel<<<NB * SEQ, 256>>>(scores);

    // 5) att[n][c][s] = sum_t attn[n][s][t] * v[n][c][t]   (output transposed)
    {
        dim3 grid(CCH / 64, SEQ / 64, NB);
        gemm_kernel<false, false, true, false, false><<<grid, 256>>>(
            scores, qkv + (size_t)2 * CCH * SEQ, att, nullptr, nullptr,
            SEQ, CCH, SEQ,
            SEQ, SEQ, SEQ,
            (long)SEQ * SEQ, (long)D3 * SEQ, (long)CCH * SEQ, 0, 1.0f);
    }

    // 6) out[n][d][s] = sum_c att[n][c][s] * w_out[d][c] + b_out[d] + x[n][d][s]
    {
        dim3 grid(CCH / 64, SEQ / 64, NB);
        gemm_kernel<true, false, true, true, true><<<grid, 256>>>(
            att, w_out, out, b_out, x,
            SEQ, CCH, CCH,
            SEQ, CCH, SEQ,
            (long)CCH * SEQ, 0, (long)CCH * SEQ, (long)CCH * SEQ, 1.0f);
    }
}

// round 9
// speedup vs baseline: 3.7204x; 3.7204x over previous
#include <cuda_runtime.h>
#include <math.h>
#include <stdint.h>

#define NB   4
#define CCH  512
#define SEQ  4096
#define D3   1536
#define GRP  32
#define CPG  16

// ---------------- scratch (static device arrays; no allocs allowed) ----------
__device__ float g_gn  [(size_t)NB*CCH*SEQ];   // groupnorm out [n][c][s]
__device__ float g_seqt[(size_t)NB*SEQ*CCH];   // [n][s][c] (tf32-rounded)
__device__ float g_qkv [(size_t)NB*SEQ*D3];    // [n][s][d] (tf32-rounded)
__device__ float g_sc  [(size_t)NB*SEQ*SEQ];   // scores / probs [n][s][t]
__device__ float g_vt  [(size_t)NB*CCH*SEQ];   // v transposed [n][c][t]
__device__ float g_att [(size_t)NB*SEQ*CCH];   // attn@V [n][s][c] (rounded)
__device__ float g_tmp [(size_t)NB*SEQ*CCH];   // proj out [n][s][c]
__device__ float g_win [D3*CCH];               // tf32-rounded w_in
__device__ float g_wout[CCH*CCH];              // tf32-rounded w_out

// ---------------- small helpers ----------------------------------------------
__device__ __forceinline__ float rna_tf32(float x) {
    float y;
    asm("cvt.rna.tf32.f32 %0, %1;" : "=f"(y) : "f"(x));
    return y;
}
__device__ __forceinline__ uint32_t smem_u32(const void* p) {
    return (uint32_t)__cvta_generic_to_shared(p);
}
__device__ __forceinline__ void cp16(uint32_t dst, const void* src) {
    asm volatile("cp.async.cg.shared.global [%0], [%1], 16;" :: "r"(dst), "l"(src));
}
__device__ __forceinline__ void mma_tf32_16x8x8(float* d,
                                                uint32_t a0, uint32_t a1, uint32_t a2, uint32_t a3,
                                                uint32_t b0, uint32_t b1) {
    asm volatile("mma.sync.aligned.m16n8k8.row.col.f32.tf32.tf32.f32 "
                 "{%0,%1,%2,%3}, {%4,%5,%6,%7}, {%8,%9}, {%0,%1,%2,%3};"
                 : "+f"(d[0]), "+f"(d[1]), "+f"(d[2]), "+f"(d[3])
                 : "r"(a0), "r"(a1), "r"(a2), "r"(a3), "r"(b0), "r"(b1));
}

// ---------------- mma.sync tf32 GEMM ------------------------------------------
// C[m,n] = alpha * sum_k A[m,k]*B[n,k] (+bias[n]); A row-major [M,K] lda,
// B row-major [N,K] ldb, C row-major ldc. M%128==0, N%128==0, K%32==0.
#define BM 128
#define BN 128
#define BK 32
#define AST 36                      // smem row stride (floats): 32 + 4 pad
#define STAGE_FLOATS (2*128*AST)    // A + B per stage = 9216 floats = 36864 B
#define TG_SMEM (2*STAGE_FLOATS*4)  // 73728 B, double buffered

template<bool HAS_BIAS, bool ROUND>
__global__ void __launch_bounds__(256, 2) tgemm_kernel(
    const float* __restrict__ A, const float* __restrict__ B, float* __restrict__ C,
    const float* __restrict__ bias,
    int K, int lda, int ldb, int ldc,
    long batchA, long batchB, long batchC, float alpha)
{
    extern __shared__ float smem[];
    const uint32_t smem_b = smem_u32(smem);
    const int tid  = threadIdx.x;
    const int lane = tid & 31;
    const int wid  = tid >> 5;
    const int wm   = wid & 3;          // 4 warps along m (32 rows each)
    const int wn   = wid >> 2;         // 2 warps along n (64 cols each)
    const int lr   = lane >> 2;        // 0..7
    const int lc   = lane & 3;         // 0..3

    A += (long)blockIdx.z * batchA;
    B += (long)blockIdx.z * batchB;
    C += (long)blockIdx.z * batchC;
    const int m0 = blockIdx.y * BM;
    const int n0 = blockIdx.x * BN;

    // global->smem chunk mapping: 1024 16B chunks per operand tile, 4/thread
    const float* aptr[4]; const float* bptr[4];
    uint32_t aoff[4], boff[4];
#pragma unroll
    for (int i = 0; i < 4; i++) {
        int idx = tid + i * 256;
        int row = idx >> 3, u = idx & 7;     // row 0..127, u = 16B chunk within 128B
        aptr[i] = A + (long)(m0 + row) * lda + u * 4;
        bptr[i] = B + (long)(n0 + row) * ldb + u * 4;
        aoff[i] = (uint32_t)(row * AST + u * 4) * 4u;
        boff[i] = (uint32_t)(128 * AST + row * AST + u * 4) * 4u;
    }

    float acc[2][8][4];
#pragma unroll
    for (int mi = 0; mi < 2; mi++)
#pragma unroll
        for (int ni = 0; ni < 8; ni++)
#pragma unroll
            for (int j = 0; j < 4; j++) acc[mi][ni][j] = 0.f;

    const int nCh = K / BK;

    // prologue: load stage 0
    {
        uint32_t sb0 = smem_b;
#pragma unroll
        for (int i = 0; i < 4; i++) cp16(sb0 + aoff[i], aptr[i]);
#pragma unroll
        for (int i = 0; i < 4; i++) cp16(sb0 + boff[i], bptr[i]);
        asm volatile("cp.async.commit_group;" ::: "memory");
    }

    for (int c = 0; c < nCh; c++) {
        if (c + 1 < nCh) {
            uint32_t sbn = smem_b + ((c + 1) & 1) * (uint32_t)(STAGE_FLOATS * 4);
            int k0 = (c + 1) * BK;
#pragma unroll
            for (int i = 0; i < 4; i++) cp16(sbn + aoff[i], aptr[i] + k0);
#pragma unroll
            for (int i = 0; i < 4; i++) cp16(sbn + boff[i], bptr[i] + k0);
            asm volatile("cp.async.commit_group;" ::: "memory");
            asm volatile("cp.async.wait_group 1;" ::: "memory");
        } else {
            asm volatile("cp.async.wait_group 0;" ::: "memory");
        }
        __syncthreads();

        const float* as = smem + (c & 1) * STAGE_FLOATS;
        const float* bs = as + 128 * AST;
#pragma unroll
        for (int k8 = 0; k8 < BK; k8 += 8) {
            uint32_t af[2][4];
#pragma unroll
            for (int mi = 0; mi < 2; mi++) {
                int r = wm * 32 + mi * 16 + lr;
                af[mi][0] = __float_as_uint(as[r * AST + k8 + lc]);
                af[mi][1] = __float_as_uint(as[(r + 8) * AST + k8 + lc]);
                af[mi][2] = __float_as_uint(as[r * AST + k8 + lc + 4]);
                af[mi][3] = __float_as_uint(as[(r + 8) * AST + k8 + lc + 4]);
            }
            uint32_t bf[8][2];
#pragma unroll
            for (int ni = 0; ni < 8; ni++) {
                int n = wn * 64 + ni * 8 + lr;
                bf[ni][0] = __float_as_uint(bs[n * AST + k8 + lc]);
                bf[ni][1] = __float_as_uint(bs[n * AST + k8 + lc + 4]);
            }
#pragma unroll
            for (int mi = 0; mi < 2; mi++)
#pragma unroll
                for (int ni = 0; ni < 8; ni++)
                    mma_tf32_16x8x8(acc[mi][ni],
                                    af[mi][0], af[mi][1], af[mi][2], af[mi][3],
                                    bf[ni][0], bf[ni][1]);
        }
        __syncthreads();
    }

    // epilogue
#pragma unroll
    for (int mi = 0; mi < 2; mi++) {
        int r0 = m0 + wm * 32 + mi * 16 + lr;
#pragma unroll
        for (int ni = 0; ni < 8; ni++) {
            int col = n0 + wn * 64 + ni * 8 + 2 * lc;
            float v0 = acc[mi][ni][0] * alpha;
            float v1 = acc[mi][ni][1] * alpha;
            float v2 = acc[mi][ni][2] * alpha;
            float v3 = acc[mi][ni][3] * alpha;
            if (HAS_BIAS) {
                float bb0 = __ldg(&bias[col]);
                float bb1 = __ldg(&bias[col + 1]);
                v0 += bb0; v1 += bb1; v2 += bb0; v3 += bb1;
            }
            if (ROUND) {
                v0 = rna_tf32(v0); v1 = rna_tf32(v1);
                v2 = rna_tf32(v2); v3 = rna_tf32(v3);
            }
            *(float2*)(C + (long)r0 * ldc + col)       = make_float2(v0, v1);
            *(float2*)(C + (long)(r0 + 8) * ldc + col) = make_float2(v2, v3);
        }
    }
}

// ---------------- block reduction helper --------------------------------------
__device__ __forceinline__ float block_reduce(float v, float* sh, bool is_max) {
    int lane = threadIdx.x & 31;
    int wd   = threadIdx.x >> 5;
#pragma unroll
    for (int o = 16; o > 0; o >>= 1) {
        float other = __shfl_xor_sync(0xffffffffu, v, o);
        v = is_max ? fmaxf(v, other) : (v + other);
    }
    if (lane == 0) sh[wd] = v;
    __syncthreads();
    if (threadIdx.x < 32) {
        float w = (threadIdx.x < 8) ? sh[threadIdx.x] : (is_max ? -3.402823e38f : 0.0f);
#pragma unroll
        for (int o = 4; o > 0; o >>= 1) {
            float other = __shfl_xor_sync(0xffffffffu, w, o);
            w = is_max ? fmaxf(w, other) : (w + other);
        }
        if (threadIdx.x == 0) sh[0] = w;
    }
    __syncthreads();
    float r = sh[0];
    __syncthreads();
    return r;
}

// ---------------- GroupNorm ----------------------------------------------------
__global__ void groupnorm_kernel(const float* __restrict__ x,
                                 const float* __restrict__ gamma,
                                 const float* __restrict__ beta,
                                 float* __restrict__ out) {
    __shared__ float sh[8];
    int n = blockIdx.x >> 5;
    int g = blockIdx.x & 31;
    const size_t base = ((size_t)n * CCH + (size_t)g * CPG) * SEQ;
    const float* xb = x + base;
    float* ob = out + base;

    float s = 0.f, s2 = 0.f;
    for (int i = threadIdx.x; i < CPG * SEQ; i += 256) {
        float v = xb[i];
        s  += v;
        s2 += v * v;
    }
    s  = block_reduce(s,  sh, false);
    s2 = block_reduce(s2, sh, false);

    const float invn = 1.0f / (float)(CPG * SEQ);
    float mean = s * invn;
    float var  = s2 * invn - mean * mean;
    float rstd = rsqrtf(var + 1e-5f);

    for (int i = threadIdx.x; i < CPG * SEQ; i += 256) {
        int c = g * CPG + (i >> 12);
        float v = (xb[i] - mean) * rstd;
        ob[i] = v * gamma[c] + beta[c];
    }
}

// ---------------- transpose (32x32 tiles) -------------------------------------
template<bool ROUND>
__global__ void transpose_kernel(const float* __restrict__ src, float* __restrict__ dst,
                                 int srcStride, int dstStride, long batchSrc, long batchDst) {
    __shared__ float t[32][33];
    src += (long)blockIdx.z * batchSrc;
    dst += (long)blockIdx.z * batchDst;
    int c0 = blockIdx.x * 32, r0 = blockIdx.y * 32;
#pragma unroll
    for (int i = 0; i < 4; i++) {
        float v = src[(long)(r0 + threadIdx.y + i*8) * srcStride + c0 + threadIdx.x];
        t[threadIdx.y + i*8][threadIdx.x] = ROUND ? rna_tf32(v) : v;
    }
    __syncthreads();
#pragma unroll
    for (int i = 0; i < 4; i++)
        dst[(long)(c0 + threadIdx.y + i*8) * dstStride + r0 + threadIdx.x] =
            t[threadIdx.x][threadIdx.y + i*8];
}

// ---------------- round-copy for weights --------------------------------------
__global__ void round_copy_kernel(const float* __restrict__ src, float* __restrict__ dst, int n) {
    int i = blockIdx.x * 256 + threadIdx.x;
    if (i < n) dst[i] = rna_tf32(src[i]);
}

// ---------------- row softmax (rounds output to tf32) --------------------------
__global__ void softmax_kernel(float* __restrict__ scores) {
    __shared__ float sh[8];
    float* p = scores + (long)blockIdx.x * SEQ;
    const int tid = threadIdx.x;

    float v[16];
    float mx = -3.402823e38f;
#pragma unroll
    for (int j = 0; j < 16; j++) {
        v[j] = p[j * 256 + tid];
        mx = fmaxf(mx, v[j]);
    }
    mx = block_reduce(mx, sh, true);

    float sum = 0.f;
#pragma unroll
    for (int j = 0; j < 16; j++) {
        v[j] = __expf(v[j] - mx);
        sum += v[j];
    }
    sum = block_reduce(sum, sh, false);
    float inv = 1.0f / sum;

#pragma unroll
    for (int j = 0; j < 16; j++)
        p[j * 256 + tid] = rna_tf32(v[j] * inv);
}

// ---------------- final: out[c][s] = tmp[s][c] + x[c][s] -----------------------
__global__ void final_kernel(const float* __restrict__ tmp, const float* __restrict__ x,
                             float* __restrict__ out) {
    __shared__ float t[32][33];
    long b = (long)blockIdx.z * (long)SEQ * CCH;
    int c0 = blockIdx.x * 32, s0 = blockIdx.y * 32;
#pragma unroll
    for (int i = 0; i < 4; i++)
        t[threadIdx.y + i*8][threadIdx.x] =
            tmp[b + (long)(s0 + threadIdx.y + i*8) * CCH + c0 + threadIdx.x];
    __syncthreads();
#pragma unroll
    for (int i = 0; i < 4; i++) {
        int cc = c0 + threadIdx.y + i*8;
        long idx = b + (long)cc * SEQ + s0 + threadIdx.x;
        out[idx] = t[threadIdx.x][threadIdx.y + i*8] + x[idx];
    }
}

// ---------------- launch -------------------------------------------------------
extern "C" void kernel_launch(void* const* d_in, const int* in_sizes, int n_in,
                              void* d_out, int out_size) {
    const float* x        = (const float*)d_in[0];
    const float* gn_scale = (const float*)d_in[1];
    const float* gn_bias  = (const float*)d_in[2];
    const float* w_in     = (const float*)d_in[3];
    const float* b_in     = (const float*)d_in[4];
    const float* w_out    = (const float*)d_in[5];
    const float* b_out    = (const float*)d_in[6];
    float* out = (float*)d_out;

    float *gn, *seqt, *qkv, *sc, *vt, *att, *tmp, *win, *wout;
    cudaGetSymbolAddress((void**)&gn,   g_gn);
    cudaGetSymbolAddress((void**)&seqt, g_seqt);
    cudaGetSymbolAddress((void**)&qkv,  g_qkv);
    cudaGetSymbolAddress((void**)&sc,   g_sc);
    cudaGetSymbolAddress((void**)&vt,   g_vt);
    cudaGetSymbolAddress((void**)&att,  g_att);
    cudaGetSymbolAddress((void**)&tmp,  g_tmp);
    cudaGetSymbolAddress((void**)&win,  g_win);
    cudaGetSymbolAddress((void**)&wout, g_wout);

    cudaFuncSetAttribute(tgemm_kernel<true,  true >, cudaFuncAttributeMaxDynamicSharedMemorySize, TG_SMEM);
    cudaFuncSetAttribute(tgemm_kernel<false, false>, cudaFuncAttributeMaxDynamicSharedMemorySize, TG_SMEM);
    cudaFuncSetAttribute(tgemm_kernel<false, true >, cudaFuncAttributeMaxDynamicSharedMemorySize, TG_SMEM);
    cudaFuncSetAttribute(tgemm_kernel<true,  false>, cudaFuncAttributeMaxDynamicSharedMemorySize, TG_SMEM);

    // 1) GroupNorm -> gn [n][c][s]
    groupnorm_kernel<<<NB * GRP, 256>>>(x, gn_scale, gn_bias, gn);

    // 2) transpose+round -> seqt [n][s][c]
    transpose_kernel<true><<<dim3(SEQ/32, CCH/32, NB), dim3(32, 8)>>>(
        gn, seqt, SEQ, CCH, (long)CCH*SEQ, (long)SEQ*CCH);

    // 3) round weights
    round_copy_kernel<<<(D3*CCH + 255)/256, 256>>>(w_in, win, D3*CCH);
    round_copy_kernel<<<(CCH*CCH + 255)/256, 256>>>(w_out, wout, CCH*CCH);

    // 4) QKV: qkv[s][d] = seqt[s][:] . win[d][:] + b_in[d]   (rounded)
    tgemm_kernel<true, true><<<dim3(D3/BN, SEQ/BM, NB), 256, TG_SMEM>>>(
        seqt, win, qkv, b_in,
        CCH, CCH, CCH, D3,
        (long)SEQ*CCH, 0, (long)SEQ*D3, 1.0f);

    // 5) scores[s][t] = scale * q[s][:] . k[t][:]
    tgemm_kernel<false, false><<<dim3(SEQ/BN, SEQ/BM, NB), 256, TG_SMEM>>>(
        qkv, qkv + 512, sc, nullptr,
        CCH, D3, D3, SEQ,
        (long)SEQ*D3, (long)SEQ*D3, (long)SEQ*SEQ, 0.044194173824159216f);

    // 6) softmax (rounds probs)
    softmax_kernel<<<NB * SEQ, 256>>>(sc);

    // 7) transpose v -> vt [n][c][t]
    transpose_kernel<false><<<dim3(CCH/32, SEQ/32, NB), dim3(32, 8)>>>(
        qkv + 1024, vt, D3, SEQ, (long)SEQ*D3, (long)CCH*SEQ);

    // 8) att[s][c] = probs[s][:] . vt[c][:]   (rounded)
    tgemm_kernel<false, true><<<dim3(CCH/BN, SEQ/BM, NB), 256, TG_SMEM>>>(
        sc, vt, att, nullptr,
        SEQ, SEQ, SEQ, CCH,
        (long)SEQ*SEQ, (long)CCH*SEQ, (long)SEQ*CCH, 1.0f);

    // 9) proj: tmp[s][c] = att[s][:] . wout[c][:] + b_out[c]
    tgemm_kernel<true, false><<<dim3(CCH/BN, SEQ/BM, NB), 256, TG_SMEM>>>(
        att, wout, tmp, b_out,
        CCH, CCH, CCH, CCH,
        (long)SEQ*CCH, 0, (long)SEQ*CCH, 1.0f);

    // 10) out[c][s] = tmp[s][c] + x[c][s]
    final_kernel<<<dim3(CCH/32, SEQ/32, NB), dim3(32, 8)>>>(tmp, x, out);
}

// round 11
// speedup vs baseline: 6.4715x; 1.7395x over previous
#include <cuda_runtime.h>
#include <cuda_bf16.h>
#include <math.h>
#include <stdint.h>

#define NB   4
#define CCH  512
#define SEQ  4096
#define D3   1536
#define GRP  32
#define CPG  16

// ---------------- scratch (static device arrays; no allocs allowed) ----------
__device__ float          g_gn [(size_t)NB*CCH*SEQ];   // groupnorm out [n][c][s] fp32
__device__ __nv_bfloat16  g_seqt[(size_t)NB*SEQ*CCH];  // [n][s][c] bf16
__device__ __nv_bfloat16  g_qkv[(size_t)NB*SEQ*D3];    // [n][s][d] bf16
__device__ float          g_sc [(size_t)NB*SEQ*SEQ];   // scores fp32 [n][s][t]
__device__ __nv_bfloat16  g_p  [(size_t)NB*SEQ*SEQ];   // probs bf16 [n][s][t]
__device__ __nv_bfloat16  g_vt [(size_t)NB*CCH*SEQ];   // v^T bf16 [n][c][t]
__device__ __nv_bfloat16  g_att[(size_t)NB*SEQ*CCH];   // attn@V bf16 [n][s][c]
__device__ float          g_tmp[(size_t)NB*SEQ*CCH];   // proj out fp32 [n][s][c]
__device__ __nv_bfloat16  g_win [D3*CCH];              // bf16 w_in
__device__ __nv_bfloat16  g_wout[CCH*CCH];             // bf16 w_out

// ---------------- small helpers ----------------------------------------------
__device__ __forceinline__ uint32_t smem_u32(const void* p) {
    return (uint32_t)__cvta_generic_to_shared(p);
}
__device__ __forceinline__ void cp16(uint32_t dst, const void* src) {
    asm volatile("cp.async.cg.shared.global [%0], [%1], 16;" :: "r"(dst), "l"(src));
}
__device__ __forceinline__ void mma_bf16_16x8x16(float* d,
                                                 uint32_t a0, uint32_t a1, uint32_t a2, uint32_t a3,
                                                 uint32_t b0, uint32_t b1) {
    asm volatile("mma.sync.aligned.m16n8k16.row.col.f32.bf16.bf16.f32 "
                 "{%0,%1,%2,%3}, {%4,%5,%6,%7}, {%8,%9}, {%0,%1,%2,%3};"
                 : "+f"(d[0]), "+f"(d[1]), "+f"(d[2]), "+f"(d[3])
                 : "r"(a0), "r"(a1), "r"(a2), "r"(a3), "r"(b0), "r"(b1));
}
__device__ __forceinline__ void store2(float* p, float a, float b) {
    *(float2*)p = make_float2(a, b);
}
__device__ __forceinline__ void store2(__nv_bfloat16* p, float a, float b) {
    *(__nv_bfloat162*)p = __floats2bfloat162_rn(a, b);
}

// ---------------- mma.sync bf16 GEMM ------------------------------------------
// C[m,n] = alpha * sum_k A[m,k]*B[n,k] (+bias[n]); A [M,K] bf16 row-major lda,
// B [N,K] bf16 row-major ldb, C row-major ldc (OutT). M,N %128==0, K%64==0.
#define BM 128
#define BN 128
#define BK 64
#define KST 72                          // smem row stride in bf16 (64 + 8 pad)
#define TILE_ELEMS (128*KST)            // 9216 bf16 per operand tile
#define STAGE_ELEMS (2*TILE_ELEMS)      // 18432 bf16 = 36864 B
#define TG_SMEM (2*STAGE_ELEMS*2)       // 73728 B double buffered

template<typename OutT, bool HAS_BIAS>
__global__ void __launch_bounds__(256, 2) bgemm_kernel(
    const __nv_bfloat16* __restrict__ A, const __nv_bfloat16* __restrict__ B,
    OutT* __restrict__ C, const float* __restrict__ bias,
    int K, int lda, int ldb, int ldc,
    long batchA, long batchB, long batchC, float alpha)
{
    extern __shared__ __nv_bfloat16 smem[];
    const uint32_t smem_b = smem_u32(smem);
    const int tid  = threadIdx.x;
    const int lane = tid & 31;
    const int wid  = tid >> 5;
    const int wm   = wid & 3;          // 4 warps along m (32 rows each)
    const int wn   = wid >> 2;         // 2 warps along n (64 cols each)
    const int lr   = lane >> 2;        // 0..7
    const int lc   = lane & 3;         // 0..3

    A += (long)blockIdx.z * batchA;
    B += (long)blockIdx.z * batchB;
    C += (long)blockIdx.z * batchC;
    const int m0 = blockIdx.y * BM;
    const int n0 = blockIdx.x * BN;

    // global->smem: 1024 16B chunks (8 bf16) per operand tile, 4/thread
    const __nv_bfloat16* aptr[4]; const __nv_bfloat16* bptr[4];
    uint32_t aoff[4], boff[4];
#pragma unroll
    for (int i = 0; i < 4; i++) {
        int idx = tid + i * 256;
        int row = idx >> 3, u = idx & 7;          // row 0..127, u = 16B chunk
        aptr[i] = A + (long)(m0 + row) * lda + u * 8;
        bptr[i] = B + (long)(n0 + row) * ldb + u * 8;
        aoff[i] = (uint32_t)(row * (KST * 2) + u * 16);
        boff[i] = (uint32_t)(TILE_ELEMS * 2 + row * (KST * 2) + u * 16);
    }

    float acc[2][8][4];
#pragma unroll
    for (int mi = 0; mi < 2; mi++)
#pragma unroll
        for (int ni = 0; ni < 8; ni++)
#pragma unroll
            for (int j = 0; j < 4; j++) acc[mi][ni][j] = 0.f;

    const int nCh = K / BK;

    // prologue: stage 0
    {
#pragma unroll
        for (int i = 0; i < 4; i++) cp16(smem_b + aoff[i], aptr[i]);
#pragma unroll
        for (int i = 0; i < 4; i++) cp16(smem_b + boff[i], bptr[i]);
        asm volatile("cp.async.commit_group;" ::: "memory");
    }

    for (int c = 0; c < nCh; c++) {
        if (c + 1 < nCh) {
            uint32_t sbn = smem_b + ((c + 1) & 1) * (uint32_t)(STAGE_ELEMS * 2);
            int k0 = (c + 1) * BK;
#pragma unroll
            for (int i = 0; i < 4; i++) cp16(sbn + aoff[i], aptr[i] + k0);
#pragma unroll
            for (int i = 0; i < 4; i++) cp16(sbn + boff[i], bptr[i] + k0);
            asm volatile("cp.async.commit_group;" ::: "memory");
            asm volatile("cp.async.wait_group 1;" ::: "memory");
        } else {
            asm volatile("cp.async.wait_group 0;" ::: "memory");
        }
        __syncthreads();

        const __nv_bfloat16* as = smem + (c & 1) * STAGE_ELEMS;
        const __nv_bfloat16* bs = as + TILE_ELEMS;
#pragma unroll
        for (int k16 = 0; k16 < BK; k16 += 16) {
            uint32_t af[2][4];
#pragma unroll
            for (int mi = 0; mi < 2; mi++) {
                int r = wm * 32 + mi * 16 + lr;
                const __nv_bfloat16* p0 = as + r * KST + k16 + 2 * lc;
                const __nv_bfloat16* p1 = as + (r + 8) * KST + k16 + 2 * lc;
                af[mi][0] = *(const uint32_t*)p0;
                af[mi][1] = *(const uint32_t*)p1;
                af[mi][2] = *(const uint32_t*)(p0 + 8);
                af[mi][3] = *(const uint32_t*)(p1 + 8);
            }
            uint32_t bf[8][2];
#pragma unroll
            for (int ni = 0; ni < 8; ni++) {
                int n = wn * 64 + ni * 8 + lr;
                const __nv_bfloat16* pb = bs + n * KST + k16 + 2 * lc;
                bf[ni][0] = *(const uint32_t*)pb;
                bf[ni][1] = *(const uint32_t*)(pb + 8);
            }
#pragma unroll
            for (int mi = 0; mi < 2; mi++)
#pragma unroll
                for (int ni = 0; ni < 8; ni++)
                    mma_bf16_16x8x16(acc[mi][ni],
                                     af[mi][0], af[mi][1], af[mi][2], af[mi][3],
                                     bf[ni][0], bf[ni][1]);
        }
        __syncthreads();
    }

    // epilogue
#pragma unroll
    for (int mi = 0; mi < 2; mi++) {
        int r0 = m0 + wm * 32 + mi * 16 + lr;
#pragma unroll
        for (int ni = 0; ni < 8; ni++) {
            int col = n0 + wn * 64 + ni * 8 + 2 * lc;
            float v0 = acc[mi][ni][0] * alpha;
            float v1 = acc[mi][ni][1] * alpha;
            float v2 = acc[mi][ni][2] * alpha;
            float v3 = acc[mi][ni][3] * alpha;
            if (HAS_BIAS) {
                float bb0 = __ldg(&bias[col]);
                float bb1 = __ldg(&bias[col + 1]);
                v0 += bb0; v1 += bb1; v2 += bb0; v3 += bb1;
            }
            store2(C + (long)r0 * ldc + col, v0, v1);
            store2(C + (long)(r0 + 8) * ldc + col, v2, v3);
        }
    }
}

// ---------------- block reduction helper --------------------------------------
__device__ __forceinline__ float block_reduce(float v, float* sh, bool is_max) {
    int lane = threadIdx.x & 31;
    int wd   = threadIdx.x >> 5;
#pragma unroll
    for (int o = 16; o > 0; o >>= 1) {
        float other = __shfl_xor_sync(0xffffffffu, v, o);
        v = is_max ? fmaxf(v, other) : (v + other);
    }
    if (lane == 0) sh[wd] = v;
    __syncthreads();
    if (threadIdx.x < 32) {
        float w = (threadIdx.x < 8) ? sh[threadIdx.x] : (is_max ? -3.402823e38f : 0.0f);
#pragma unroll
        for (int o = 4; o > 0; o >>= 1) {
            float other = __shfl_xor_sync(0xffffffffu, w, o);
            w = is_max ? fmaxf(w, other) : (w + other);
        }
        if (threadIdx.x == 0) sh[0] = w;
    }
    __syncthreads();
    float r = sh[0];
    __syncthreads();
    return r;
}

// ---------------- GroupNorm ----------------------------------------------------
__global__ void groupnorm_kernel(const float* __restrict__ x,
                                 const float* __restrict__ gamma,
                                 const float* __restrict__ beta,
                                 float* __restrict__ out) {
    __shared__ float sh[8];
    int n = blockIdx.x >> 5;
    int g = blockIdx.x & 31;
    const size_t base = ((size_t)n * CCH + (size_t)g * CPG) * SEQ;
    const float* xb = x + base;
    float* ob = out + base;

    float s = 0.f, s2 = 0.f;
    for (int i = threadIdx.x; i < CPG * SEQ; i += 256) {
        float v = xb[i];
        s  += v;
        s2 += v * v;
    }
    s  = block_reduce(s,  sh, false);
    s2 = block_reduce(s2, sh, false);

    const float invn = 1.0f / (float)(CPG * SEQ);
    float mean = s * invn;
    float var  = s2 * invn - mean * mean;
    float rstd = rsqrtf(var + 1e-5f);

    for (int i = threadIdx.x; i < CPG * SEQ; i += 256) {
        int c = g * CPG + (i >> 12);
        float v = (xb[i] - mean) * rstd;
        ob[i] = v * gamma[c] + beta[c];
    }
}

// ---------------- transpose (32x32 tiles), with dtype conversion ---------------
template<typename InT, typename OutT>
__global__ void transpose_kernel(const InT* __restrict__ src, OutT* __restrict__ dst,
                                 int srcStride, int dstStride, long batchSrc, long batchDst) {
    __shared__ float t[32][33];
    src += (long)blockIdx.z * batchSrc;
    dst += (long)blockIdx.z * batchDst;
    int c0 = blockIdx.x * 32, r0 = blockIdx.y * 32;
#pragma unroll
    for (int i = 0; i < 4; i++)
        t[threadIdx.y + i*8][threadIdx.x] =
            (float)src[(long)(r0 + threadIdx.y + i*8) * srcStride + c0 + threadIdx.x];
    __syncthreads();
#pragma unroll
    for (int i = 0; i < 4; i++)
        dst[(long)(c0 + threadIdx.y + i*8) * dstStride + r0 + threadIdx.x] =
            (OutT)t[threadIdx.x][threadIdx.y + i*8];
}

// ---------------- convert weights fp32 -> bf16 ---------------------------------
__global__ void convert_kernel(const float* __restrict__ src, __nv_bfloat16* __restrict__ dst, int n) {
    int i = blockIdx.x * 256 + threadIdx.x;
    if (i < n) dst[i] = __float2bfloat16_rn(src[i]);
}

// ---------------- row softmax: fp32 scores -> bf16 probs -----------------------
__global__ void softmax_kernel(const float* __restrict__ scores, __nv_bfloat16* __restrict__ probs) {
    __shared__ float sh[8];
    const float* p = scores + (long)blockIdx.x * SEQ;
    __nv_bfloat16* q = probs + (long)blockIdx.x * SEQ;
    const int tid = threadIdx.x;

    float v[16];
    float mx = -3.402823e38f;
#pragma unroll
    for (int j = 0; j < 16; j++) {
        v[j] = p[j * 256 + tid];
        mx = fmaxf(mx, v[j]);
    }
    mx = block_reduce(mx, sh, true);

    float sum = 0.f;
#pragma unroll
    for (int j = 0; j < 16; j++) {
        v[j] = __expf(v[j] - mx);
        sum += v[j];
    }
    sum = block_reduce(sum, sh, false);
    float inv = 1.0f / sum;

#pragma unroll
    for (int j = 0; j < 16; j++)
        q[j * 256 + tid] = __float2bfloat16_rn(v[j] * inv);
}

// ---------------- final: out[c][s] = tmp[s][c] + x[c][s] -----------------------
__global__ void final_kernel(const float* __restrict__ tmp, const float* __restrict__ x,
                             float* __restrict__ out) {
    __shared__ float t[32][33];
    long b = (long)blockIdx.z * (long)SEQ * CCH;
    int c0 = blockIdx.x * 32, s0 = blockIdx.y * 32;
#pragma unroll
    for (int i = 0; i < 4; i++)
        t[threadIdx.y + i*8][threadIdx.x] =
            tmp[b + (long)(s0 + threadIdx.y + i*8) * CCH + c0 + threadIdx.x];
    __syncthreads();
#pragma unroll
    for (int i = 0; i < 4; i++) {
        int cc = c0 + threadIdx.y + i*8;
        long idx = b + (long)cc * SEQ + s0 + threadIdx.x;
        out[idx] = t[threadIdx.x][threadIdx.y + i*8] + x[idx];
    }
}

// ---------------- launch -------------------------------------------------------
extern "C" void kernel_launch(void* const* d_in, const int* in_sizes, int n_in,
                              void* d_out, int out_size) {
    const float* x        = (const float*)d_in[0];
    const float* gn_scale = (const float*)d_in[1];
    const float* gn_bias  = (const float*)d_in[2];
    const float* w_in     = (const float*)d_in[3];
    const float* b_in     = (const float*)d_in[4];
    const float* w_out    = (const float*)d_in[5];
    const float* b_out    = (const float*)d_in[6];
    float* out = (float*)d_out;

    float *gn, *sc, *tmp;
    __nv_bfloat16 *seqt, *qkv, *pp, *vt, *att, *win, *wout;
    cudaGetSymbolAddress((void**)&gn,   g_gn);
    cudaGetSymbolAddress((void**)&seqt, g_seqt);
    cudaGetSymbolAddress((void**)&qkv,  g_qkv);
    cudaGetSymbolAddress((void**)&sc,   g_sc);
    cudaGetSymbolAddress((void**)&pp,   g_p);
    cudaGetSymbolAddress((void**)&vt,   g_vt);
    cudaGetSymbolAddress((void**)&att,  g_att);
    cudaGetSymbolAddress((void**)&tmp,  g_tmp);
    cudaGetSymbolAddress((void**)&win,  g_win);
    cudaGetSymbolAddress((void**)&wout, g_wout);

    cudaFuncSetAttribute(bgemm_kernel<__nv_bfloat16, true >, cudaFuncAttributeMaxDynamicSharedMemorySize, TG_SMEM);
    cudaFuncSetAttribute(bgemm_kernel<__nv_bfloat16, false>, cudaFuncAttributeMaxDynamicSharedMemorySize, TG_SMEM);
    cudaFuncSetAttribute(bgemm_kernel<float, true >,         cudaFuncAttributeMaxDynamicSharedMemorySize, TG_SMEM);
    cudaFuncSetAttribute(bgemm_kernel<float, false>,         cudaFuncAttributeMaxDynamicSharedMemorySize, TG_SMEM);

    // 1) GroupNorm -> gn [n][c][s] fp32
    groupnorm_kernel<<<NB * GRP, 256>>>(x, gn_scale, gn_bias, gn);

    // 2) transpose+convert -> seqt [n][s][c] bf16
    transpose_kernel<float, __nv_bfloat16><<<dim3(SEQ/32, CCH/32, NB), dim3(32, 8)>>>(
        gn, seqt, SEQ, CCH, (long)CCH*SEQ, (long)SEQ*CCH);

    // 3) convert weights -> bf16
    convert_kernel<<<(D3*CCH + 255)/256, 256>>>(w_in, win, D3*CCH);
    convert_kernel<<<(CCH*CCH + 255)/256, 256>>>(w_out, wout, CCH*CCH);

    // 4) QKV: qkv[s][d] = seqt[s][:] . win[d][:] + b_in[d]  (bf16 out)
    bgemm_kernel<__nv_bfloat16, true><<<dim3(D3/BN, SEQ/BM, NB), 256, TG_SMEM>>>(
        seqt, win, qkv, b_in,
        CCH, CCH, CCH, D3,
        (long)SEQ*CCH, 0, (long)SEQ*D3, 1.0f);

    // 5) scores[s][t] = scale * q[s][:] . k[t][:]  (fp32 out)
    bgemm_kernel<float, false><<<dim3(SEQ/BN, SEQ/BM, NB), 256, TG_SMEM>>>(
        qkv, qkv + 512, sc, nullptr,
        CCH, D3, D3, SEQ,
        (long)SEQ*D3, (long)SEQ*D3, (long)SEQ*SEQ, 0.044194173824159216f);

    // 6) softmax: fp32 scores -> bf16 probs
    softmax_kernel<<<NB * SEQ, 256>>>(sc, pp);

    // 7) transpose v -> vt [n][c][t] bf16
    transpose_kernel<__nv_bfloat16, __nv_bfloat16><<<dim3(CCH/32, SEQ/32, NB), dim3(32, 8)>>>(
        qkv + 1024, vt, D3, SEQ, (long)SEQ*D3, (long)CCH*SEQ);

    // 8) att[s][c] = probs[s][:] . vt[c][:]  (bf16 out)
    bgemm_kernel<__nv_bfloat16, false><<<dim3(CCH/BN, SEQ/BM, NB), 256, TG_SMEM>>>(
        pp, vt, att, nullptr,
        SEQ, SEQ, SEQ, CCH,
        (long)SEQ*SEQ, (long)CCH*SEQ, (long)SEQ*CCH, 1.0f);

    // 9) proj: tmp[s][c] = att[s][:] . wout[c][:] + b_out[c]  (fp32 out)
    bgemm_kernel<float, true><<<dim3(CCH/BN, SEQ/BM, NB), 256, TG_SMEM>>>(
        att, wout, tmp, b_out,
        CCH, CCH, CCH, CCH,
        (long)SEQ*CCH, 0, (long)SEQ*CCH, 1.0f);

    // 10) out[c][s] = tmp[s][c] + x[c][s]
    final_kernel<<<dim3(CCH/32, SEQ/32, NB), dim3(32, 8)>>>(tmp, x, out);
}

// round 15
// speedup vs baseline: 6.9634x; 1.0760x over previous
#include <cuda_runtime.h>
#include <cuda_bf16.h>
#include <math.h>
#include <stdint.h>

#define NB   4
#define CCH  512
#define SEQ  4096
#define D3   1536
#define GRP  32
#define CPG  16

// ---------------- scratch (static device arrays; no allocs allowed) ----------
__device__ float          g_gn [(size_t)NB*CCH*SEQ];   // groupnorm out [n][c][s] fp32
__device__ __nv_bfloat16  g_seqt[(size_t)NB*SEQ*CCH];  // [n][s][c] bf16
__device__ __nv_bfloat16  g_qkv[(size_t)NB*SEQ*D3];    // [n][s][d] bf16
__device__ float          g_sc [(size_t)NB*SEQ*SEQ];   // scores fp32 [n][s][t]
__device__ __nv_bfloat16  g_p  [(size_t)NB*SEQ*SEQ];   // probs bf16 [n][s][t]
__device__ __nv_bfloat16  g_vt [(size_t)NB*CCH*SEQ];   // v^T bf16 [n][c][t]
__device__ __nv_bfloat16  g_att[(size_t)NB*SEQ*CCH];   // attn@V bf16 [n][s][c]
__device__ float          g_tmp[(size_t)NB*SEQ*CCH];   // proj out fp32 [n][s][c]
__device__ __nv_bfloat16  g_win [D3*CCH];              // bf16 w_in
__device__ __nv_bfloat16  g_wout[CCH*CCH];             // bf16 w_out

// ---------------- small helpers ----------------------------------------------
__device__ __forceinline__ uint32_t smem_u32(const void* p) {
    return (uint32_t)__cvta_generic_to_shared(p);
}
__device__ __forceinline__ void cp16(uint32_t dst, const void* src) {
    asm volatile("cp.async.cg.shared.global [%0], [%1], 16;" :: "r"(dst), "l"(src));
}
__device__ __forceinline__ void ldsm_x4(uint32_t& r0, uint32_t& r1, uint32_t& r2, uint32_t& r3,
                                        uint32_t addr) {
    asm volatile("ldmatrix.sync.aligned.m8n8.x4.shared.b16 {%0,%1,%2,%3}, [%4];"
                 : "=r"(r0), "=r"(r1), "=r"(r2), "=r"(r3) : "r"(addr));
}
__device__ __forceinline__ void mma_bf16_16x8x16(float* d,
                                                 uint32_t a0, uint32_t a1, uint32_t a2, uint32_t a3,
                                                 uint32_t b0, uint32_t b1) {
    asm volatile("mma.sync.aligned.m16n8k16.row.col.f32.bf16.bf16.f32 "
                 "{%0,%1,%2,%3}, {%4,%5,%6,%7}, {%8,%9}, {%0,%1,%2,%3};"
                 : "+f"(d[0]), "+f"(d[1]), "+f"(d[2]), "+f"(d[3])
                 : "r"(a0), "r"(a1), "r"(a2), "r"(a3), "r"(b0), "r"(b1));
}
__device__ __forceinline__ void store2(float* p, float a, float b) {
    *(float2*)p = make_float2(a, b);
}
__device__ __forceinline__ void store2(__nv_bfloat16* p, float a, float b) {
    *(__nv_bfloat162*)p = __floats2bfloat162_rn(a, b);
}

// ---------------- mma.sync bf16 GEMM (ldmatrix feed) ---------------------------
// C[m,n] = alpha * sum_k A[m,k]*B[n,k] (+bias[n]); A [M,K] bf16 row-major lda,
// B [N,K] bf16 row-major ldb, C row-major ldc (OutT). M,N %128==0, K%64==0.
#define BM 128
#define BN 128
#define BK 64
#define KST 72                          // smem row stride in bf16 (64 + 8 pad)
#define TILE_ELEMS (128*KST)            // 9216 bf16 per operand tile
#define STAGE_ELEMS (2*TILE_ELEMS)      // 18432 bf16 = 36864 B
#define TG_SMEM (2*STAGE_ELEMS*2)       // 73728 B double buffered

template<typename OutT, bool HAS_BIAS>
__global__ void __launch_bounds__(256, 2) bgemm_kernel(
    const __nv_bfloat16* __restrict__ A, const __nv_bfloat16* __restrict__ B,
    OutT* __restrict__ C, const float* __restrict__ bias,
    int K, int lda, int ldb, int ldc,
    long batchA, long batchB, long batchC, float alpha)
{
    extern __shared__ __nv_bfloat16 smem[];
    const uint32_t smem_b = smem_u32(smem);
    const int tid  = threadIdx.x;
    const int lane = tid & 31;
    const int wid  = tid >> 5;
    const int wm   = wid & 3;          // 4 warps along m (32 rows each)
    const int wn   = wid >> 2;         // 2 warps along n (64 cols each)
    const int lr   = lane >> 2;        // 0..7
    const int lc   = lane & 3;         // 0..3

    A += (long)blockIdx.z * batchA;
    B += (long)blockIdx.z * batchB;
    C += (long)blockIdx.z * batchC;
    const int m0 = blockIdx.y * BM;
    const int n0 = blockIdx.x * BN;

    // global->smem: 1024 16B chunks (8 bf16) per operand tile, 4/thread
    const __nv_bfloat16* aptr[4]; const __nv_bfloat16* bptr[4];
    uint32_t aoff[4], boff[4];
#pragma unroll
    for (int i = 0; i < 4; i++) {
        int idx = tid + i * 256;
        int row = idx >> 3, u = idx & 7;          // row 0..127, u = 16B chunk
        aptr[i] = A + (long)(m0 + row) * lda + u * 8;
        bptr[i] = B + (long)(n0 + row) * ldb + u * 8;
        aoff[i] = (uint32_t)(row * (KST * 2) + u * 16);
        boff[i] = (uint32_t)(TILE_ELEMS * 2 + row * (KST * 2) + u * 16);
    }

    // ldmatrix per-thread source rows (byte offsets within tile)
    // A x4: lanes 0-15 -> rows mbase+(lane&15), k16 ; lanes 16-31 -> same rows, k16+8
    const uint32_t a_row = (uint32_t)(lane & 15);
    const uint32_t a_kof = (uint32_t)((lane >> 4) * 8);
    // B x4 (per ni-pair): group=lane>>3: (n-half, k-half) = (g>>1, g&1)
    const uint32_t b_row = (uint32_t)(((lane >> 4) * 8) + (lane & 7));
    const uint32_t b_kof = (uint32_t)(((lane >> 3) & 1) * 8);

    float acc[2][8][4];
#pragma unroll
    for (int mi = 0; mi < 2; mi++)
#pragma unroll
        for (int ni = 0; ni < 8; ni++)
#pragma unroll
            for (int j = 0; j < 4; j++) acc[mi][ni][j] = 0.f;

    const int nCh = K / BK;

    // prologue: stage 0
    {
#pragma unroll
        for (int i = 0; i < 4; i++) cp16(smem_b + aoff[i], aptr[i]);
#pragma unroll
        for (int i = 0; i < 4; i++) cp16(smem_b + boff[i], bptr[i]);
        asm volatile("cp.async.commit_group;" ::: "memory");
    }

    for (int c = 0; c < nCh; c++) {
        if (c + 1 < nCh) {
            uint32_t sbn = smem_b + ((c + 1) & 1) * (uint32_t)(STAGE_ELEMS * 2);
            int k0 = (c + 1) * BK;
#pragma unroll
            for (int i = 0; i < 4; i++) cp16(sbn + aoff[i], aptr[i] + k0);
#pragma unroll
            for (int i = 0; i < 4; i++) cp16(sbn + boff[i], bptr[i] + k0);
            asm volatile("cp.async.commit_group;" ::: "memory");
            asm volatile("cp.async.wait_group 1;" ::: "memory");
        } else {
            asm volatile("cp.async.wait_group 0;" ::: "memory");
        }
        __syncthreads();

        const uint32_t as_u = smem_b + (uint32_t)((c & 1) * STAGE_ELEMS * 2);
        const uint32_t bs_u = as_u + (uint32_t)(TILE_ELEMS * 2);
#pragma unroll
        for (int k16 = 0; k16 < BK; k16 += 16) {
            uint32_t af[2][4];
#pragma unroll
            for (int mi = 0; mi < 2; mi++) {
                uint32_t addr = as_u +
                    ((uint32_t)(wm * 32 + mi * 16) + a_row) * (KST * 2) +
                    ((uint32_t)k16 + a_kof) * 2;
                ldsm_x4(af[mi][0], af[mi][1], af[mi][2], af[mi][3], addr);
            }
            uint32_t bf[8][2];
#pragma unroll
            for (int j = 0; j < 4; j++) {
                uint32_t addr = bs_u +
                    ((uint32_t)(wn * 64 + j * 16) + b_row) * (KST * 2) +
                    ((uint32_t)k16 + b_kof) * 2;
                ldsm_x4(bf[2*j][0], bf[2*j][1], bf[2*j+1][0], bf[2*j+1][1], addr);
            }
#pragma unroll
            for (int mi = 0; mi < 2; mi++)
#pragma unroll
                for (int ni = 0; ni < 8; ni++)
                    mma_bf16_16x8x16(acc[mi][ni],
                                     af[mi][0], af[mi][1], af[mi][2], af[mi][3],
                                     bf[ni][0], bf[ni][1]);
        }
        __syncthreads();
    }

    // epilogue
#pragma unroll
    for (int mi = 0; mi < 2; mi++) {
        int r0 = m0 + wm * 32 + mi * 16 + lr;
#pragma unroll
        for (int ni = 0; ni < 8; ni++) {
            int col = n0 + wn * 64 + ni * 8 + 2 * lc;
            float v0 = acc[mi][ni][0] * alpha;
            float v1 = acc[mi][ni][1] * alpha;
            float v2 = acc[mi][ni][2] * alpha;
            float v3 = acc[mi][ni][3] * alpha;
            if (HAS_BIAS) {
                float bb0 = __ldg(&bias[col]);
                float bb1 = __ldg(&bias[col + 1]);
                v0 += bb0; v1 += bb1; v2 += bb0; v3 += bb1;
            }
            store2(C + (long)r0 * ldc + col, v0, v1);
            store2(C + (long)(r0 + 8) * ldc + col, v2, v3);
        }
    }
}

// ---------------- block reduction helper --------------------------------------
__device__ __forceinline__ float block_reduce(float v, float* sh, bool is_max) {
    int lane = threadIdx.x & 31;
    int wd   = threadIdx.x >> 5;
#pragma unroll
    for (int o = 16; o > 0; o >>= 1) {
        float other = __shfl_xor_sync(0xffffffffu, v, o);
        v = is_max ? fmaxf(v, other) : (v + other);
    }
    if (lane == 0) sh[wd] = v;
    __syncthreads();
    if (threadIdx.x < 32) {
        float w = (threadIdx.x < 8) ? sh[threadIdx.x] : (is_max ? -3.402823e38f : 0.0f);
#pragma unroll
        for (int o = 4; o > 0; o >>= 1) {
            float other = __shfl_xor_sync(0xffffffffu, w, o);
            w = is_max ? fmaxf(w, other) : (w + other);
        }
        if (threadIdx.x == 0) sh[0] = w;
    }
    __syncthreads();
    float r = sh[0];
    __syncthreads();
    return r;
}

// ---------------- GroupNorm ----------------------------------------------------
__global__ void groupnorm_kernel(const float* __restrict__ x,
                                 const float* __restrict__ gamma,
                                 const float* __restrict__ beta,
                                 float* __restrict__ out) {
    __shared__ float sh[8];
    int n = blockIdx.x >> 5;
    int g = blockIdx.x & 31;
    const size_t base = ((size_t)n * CCH + (size_t)g * CPG) * SEQ;
    const float* xb = x + base;
    float* ob = out + base;

    float s = 0.f, s2 = 0.f;
    for (int i = threadIdx.x; i < CPG * SEQ; i += 256) {
        float v = xb[i];
        s  += v;
        s2 += v * v;
    }
    s  = block_reduce(s,  sh, false);
    s2 = block_reduce(s2, sh, false);

    const float invn = 1.0f / (float)(CPG * SEQ);
    float mean = s * invn;
    float var  = s2 * invn - mean * mean;
    float rstd = rsqrtf(var + 1e-5f);

    for (int i = threadIdx.x; i < CPG * SEQ; i += 256) {
        int c = g * CPG + (i >> 12);
        float v = (xb[i] - mean) * rstd;
        ob[i] = v * gamma[c] + beta[c];
    }
}

// ---------------- transpose (32x32 tiles), with dtype conversion ---------------
template<typename InT, typename OutT>
__global__ void transpose_kernel(const InT* __restrict__ src, OutT* __restrict__ dst,
                                 int srcStride, int dstStride, long batchSrc, long batchDst) {
    __shared__ float t[32][33];
    src += (long)blockIdx.z * batchSrc;
    dst += (long)blockIdx.z * batchDst;
    int c0 = blockIdx.x * 32, r0 = blockIdx.y * 32;
#pragma unroll
    for (int i = 0; i < 4; i++)
        t[threadIdx.y + i*8][threadIdx.x] =
            (float)src[(long)(r0 + threadIdx.y + i*8) * srcStride + c0 + threadIdx.x];
    __syncthreads();
#pragma unroll
    for (int i = 0; i < 4; i++)
        dst[(long)(c0 + threadIdx.y + i*8) * dstStride + r0 + threadIdx.x] =
            (OutT)t[threadIdx.x][threadIdx.y + i*8];
}

// ---------------- convert weights fp32 -> bf16 ---------------------------------
__global__ void convert_kernel(const float* __restrict__ src, __nv_bfloat16* __restrict__ dst, int n) {
    int i = blockIdx.x * 256 + threadIdx.x;
    if (i < n) dst[i] = __float2bfloat16_rn(src[i]);
}

// ---------------- row softmax: fp32 scores -> bf16 probs -----------------------
__global__ void softmax_kernel(const float* __restrict__ scores, __nv_bfloat16* __restrict__ probs) {
    __shared__ float sh[8];
    const float* p = scores + (long)blockIdx.x * SEQ;
    __nv_bfloat16* q = probs + (long)blockIdx.x * SEQ;
    const int tid = threadIdx.x;

    float v[16];
    float mx = -3.402823e38f;
#pragma unroll
    for (int j = 0; j < 16; j++) {
        v[j] = p[j * 256 + tid];
        mx = fmaxf(mx, v[j]);
    }
    mx = block_reduce(mx, sh, true);

    float sum = 0.f;
#pragma unroll
    for (int j = 0; j < 16; j++) {
        v[j] = __expf(v[j] - mx);
        sum += v[j];
    }
    sum = block_reduce(sum, sh, false);
    float inv = 1.0f / sum;

#pragma unroll
    for (int j = 0; j < 16; j++)
        q[j * 256 + tid] = __float2bfloat16_rn(v[j] * inv);
}

// ---------------- final: out[c][s] = tmp[s][c] + x[c][s] -----------------------
__global__ void final_kernel(const float* __restrict__ tmp, const float* __restrict__ x,
                             float* __restrict__ out) {
    __shared__ float t[32][33];
    long b = (long)blockIdx.z * (long)SEQ * CCH;
    int c0 = blockIdx.x * 32, s0 = blockIdx.y * 32;
#pragma unroll
    for (int i = 0; i < 4; i++)
        t[threadIdx.y + i*8][threadIdx.x] =
            tmp[b + (long)(s0 + threadIdx.y + i*8) * CCH + c0 + threadIdx.x];
    __syncthreads();
#pragma unroll
    for (int i = 0; i < 4; i++) {
        int cc = c0 + threadIdx.y + i*8;
        long idx = b + (long)cc * SEQ + s0 + threadIdx.x;
        out[idx] = t[threadIdx.x][threadIdx.y + i*8] + x[idx];
    }
}

// ---------------- launch -------------------------------------------------------
extern "C" void kernel_launch(void* const* d_in, const int* in_sizes, int n_in,
                              void* d_out, int out_size) {
    const float* x        = (const float*)d_in[0];
    const float* gn_scale = (const float*)d_in[1];
    const float* gn_bias  = (const float*)d_in[2];
    const float* w_in     = (const float*)d_in[3];
    const float* b_in     = (const float*)d_in[4];
    const float* w_out    = (const float*)d_in[5];
    const float* b_out    = (const float*)d_in[6];
    float* out = (float*)d_out;

    float *gn, *sc, *tmp;
    __nv_bfloat16 *seqt, *qkv, *pp, *vt, *att, *win, *wout;
    cudaGetSymbolAddress((void**)&gn,   g_gn);
    cudaGetSymbolAddress((void**)&seqt, g_seqt);
    cudaGetSymbolAddress((void**)&qkv,  g_qkv);
    cudaGetSymbolAddress((void**)&sc,   g_sc);
    cudaGetSymbolAddress((void**)&pp,   g_p);
    cudaGetSymbolAddress((void**)&vt,   g_vt);
    cudaGetSymbolAddress((void**)&att,  g_att);
    cudaGetSymbolAddress((void**)&tmp,  g_tmp);
    cudaGetSymbolAddress((void**)&win,  g_win);
    cudaGetSymbolAddress((void**)&wout, g_wout);

    cudaFuncSetAttribute(bgemm_kernel<__nv_bfloat16, true >, cudaFuncAttributeMaxDynamicSharedMemorySize, TG_SMEM);
    cudaFuncSetAttribute(bgemm_kernel<__nv_bfloat16, false>, cudaFuncAttributeMaxDynamicSharedMemorySize, TG_SMEM);
    cudaFuncSetAttribute(bgemm_kernel<float, true >,         cudaFuncAttributeMaxDynamicSharedMemorySize, TG_SMEM);
    cudaFuncSetAttribute(bgemm_kernel<float, false>,         cudaFuncAttributeMaxDynamicSharedMemorySize, TG_SMEM);

    // 1) GroupNorm -> gn [n][c][s] fp32
    groupnorm_kernel<<<NB * GRP, 256>>>(x, gn_scale, gn_bias, gn);

    // 2) transpose+convert -> seqt [n][s][c] bf16
    transpose_kernel<float, __nv_bfloat16><<<dim3(SEQ/32, CCH/32, NB), dim3(32, 8)>>>(
        gn, seqt, SEQ, CCH, (long)CCH*SEQ, (long)SEQ*CCH);

    // 3) convert weights -> bf16
    convert_kernel<<<(D3*CCH + 255)/256, 256>>>(w_in, win, D3*CCH);
    convert_kernel<<<(CCH*CCH + 255)/256, 256>>>(w_out, wout, CCH*CCH);

    // 4) QKV: qkv[s][d] = seqt[s][:] . win[d][:] + b_in[d]  (bf16 out)
    bgemm_kernel<__nv_bfloat16, true><<<dim3(D3/BN, SEQ/BM, NB), 256, TG_SMEM>>>(
        seqt, win, qkv, b_in,
        CCH, CCH, CCH, D3,
        (long)SEQ*CCH, 0, (long)SEQ*D3, 1.0f);

    // 5) scores[s][t] = scale * q[s][:] . k[t][:]  (fp32 out)
    bgemm_kernel<float, false><<<dim3(SEQ/BN, SEQ/BM, NB), 256, TG_SMEM>>>(
        qkv, qkv + 512, sc, nullptr,
        CCH, D3, D3, SEQ,
        (long)SEQ*D3, (long)SEQ*D3, (long)SEQ*SEQ, 0.044194173824159216f);

    // 6) softmax: fp32 scores -> bf16 probs
    softmax_kernel<<<NB * SEQ, 256>>>(sc, pp);

    // 7) transpose v -> vt [n][c][t] bf16
    transpose_kernel<__nv_bfloat16, __nv_bfloat16><<<dim3(CCH/32, SEQ/32, NB), dim3(32, 8)>>>(
        qkv + 1024, vt, D3, SEQ, (long)SEQ*D3, (long)CCH*SEQ);

    // 8) att[s][c] = probs[s][:] . vt[c][:]  (bf16 out)
    bgemm_kernel<__nv_bfloat16, false><<<dim3(CCH/BN, SEQ/BM, NB), 256, TG_SMEM>>>(
        pp, vt, att, nullptr,
        SEQ, SEQ, SEQ, CCH,
        (long)SEQ*SEQ, (long)CCH*SEQ, (long)SEQ*CCH, 1.0f);

    // 9) proj: tmp[s][c] = att[s][:] . wout[c][:] + b_out[c]  (fp32 out)
    bgemm_kernel<float, true><<<dim3(CCH/BN, SEQ/BM, NB), 256, TG_SMEM>>>(
        att, wout, tmp, b_out,
        CCH, CCH, CCH, CCH,
        (long)SEQ*CCH, 0, (long)SEQ*CCH, 1.0f);

    // 10) out[c][s] = tmp[s][c] + x[c][s]
    final_kernel<<<dim3(CCH/32, SEQ/32, NB), dim3(32, 8)>>>(tmp, x, out);
}